// round 14
// baseline (speedup 1.0000x reference)
#include <cuda_runtime.h>
#include <cstdint>

// Problem constants (fixed by reference setup_inputs)
#define B_SZ 16
#define S_SZ 4096
#define D_SZ 512
#define PE_VEC 64                 // float4 per pe row (256 floats)
#define TPB 256
#define PAIRS 2                   // 32B pairs per thread (64B/thread, as R6)

// 256-bit store with streaming eviction priority (v8 form required for hints)
__device__ __forceinline__ void stg_v8_cs(float4* p, const float4& a, const float4& b) {
    asm volatile("st.global.L2::evict_first.v8.b32 [%0], {%1,%2,%3,%4,%5,%6,%7,%8};"
                 :: "l"(p),
                    "r"(__float_as_uint(a.x)), "r"(__float_as_uint(a.y)),
                    "r"(__float_as_uint(a.z)), "r"(__float_as_uint(a.w)),
                    "r"(__float_as_uint(b.x)), "r"(__float_as_uint(b.y)),
                    "r"(__float_as_uint(b.z)), "r"(__float_as_uint(b.w))
                 : "memory");
}

// ---------------------------------------------------------------------------
// R6 body with ONLY the store side widened to STG.256. Loads remain 4x
// __ldcs LDG.128 (proven). Per thread: 2 contiguous float4-pairs.
// Block covers 1024 float4 = 8 s-rows; 512 blocks per batch (b = blk >> 9).
// ---------------------------------------------------------------------------
__global__ void __launch_bounds__(TPB) fused_pe_kernel(
    const float4* __restrict__ x,
    const int4*   __restrict__ mask,  // (16, 1024) int4
    const float4* __restrict__ pe,    // (5000, 64) float4
    float4* __restrict__ out
) {
    const int tid   = threadIdx.x;
    const int base8 = blockIdx.x * (TPB * PAIRS) + tid;   // 32B-pair index
    const int b     = blockIdx.x >> 9;                    // 512 blocks per batch

    // 1) Mask loads first (head of the longest dependency chain)
    const int4* m = mask + b * (S_SZ / 4);
    int4 mv[4];
    #pragma unroll
    for (int k = 0; k < 4; k++)
        mv[k] = __ldg(&m[k * TPB + tid]);

    // 2) Front-batch all x loads: 4x LDG.128, streaming evict-first
    float4 xv[2 * PAIRS];
    #pragma unroll
    for (int k = 0; k < PAIRS; k++) {
        const int i = (base8 + k * TPB) << 1;   // float4 index of pair start
        xv[2*k]   = __ldcs(&x[i]);
        xv[2*k+1] = __ldcs(&x[i + 1]);
    }

    // 3) Base-pe adds (pair shares s; c4 even, pair covers c4, c4+1)
    int s_arr[PAIRS], c4_arr[PAIRS];
    #pragma unroll
    for (int k = 0; k < PAIRS; k++) {
        const int i = (base8 + k * TPB) << 1;
        s_arr[k]  = (i >> 7) & (S_SZ - 1);
        c4_arr[k] = i & (PE_VEC - 1);
        const float4* prow = pe + s_arr[k] * PE_VEC + c4_arr[k];
        const float4 b0 = prow[0], b1 = prow[1];
        xv[2*k].x   += b0.x; xv[2*k].y   += b0.y; xv[2*k].z   += b0.z; xv[2*k].w   += b0.w;
        xv[2*k+1].x += b1.x; xv[2*k+1].y += b1.y; xv[2*k+1].z += b1.z; xv[2*k+1].w += b1.w;
    }

    // 4) L = S - sum(mask): pure adds + REDUX + one BAR
    int ones = ((mv[0].x + mv[0].y) + (mv[0].z + mv[0].w))
             + ((mv[1].x + mv[1].y) + (mv[1].z + mv[1].w))
             + ((mv[2].x + mv[2].y) + (mv[2].z + mv[2].w))
             + ((mv[3].x + mv[3].y) + (mv[3].z + mv[3].w));
    ones = __reduce_add_sync(0xFFFFFFFFu, ones);

    __shared__ __align__(16) int warp_sums[8];   // TPB/32 = 8 warps
    if ((tid & 31) == 0) warp_sums[tid >> 5] = ones;
    __syncthreads();

    const int4* ws = reinterpret_cast<const int4*>(warp_sums);
    const int4 w0 = ws[0], w1 = ws[1];
    const int L = S_SZ - (((w0.x + w0.y) + (w0.z + w0.w))
                        + ((w1.x + w1.y) + (w1.z + w1.w)));

    // 5) Reversed-feature pe: pair -> row L-1-s, cols 63-c4 (for pair[0]),
    //    62-c4 (for pair[1]), lanes reversed within each float4
    #pragma unroll
    for (int k = 0; k < PAIRS; k++) {
        const int s = s_arr[k];
        if (s < L) {
            const float4* rrow = pe + (L - 1 - s) * PE_VEC;
            const float4 r1 = rrow[PE_VEC - 1 - c4_arr[k]];
            const float4 r0 = rrow[PE_VEC - 2 - c4_arr[k]];
            xv[2*k].x   += r1.w; xv[2*k].y   += r1.z; xv[2*k].z   += r1.y; xv[2*k].w   += r1.x;
            xv[2*k+1].x += r0.w; xv[2*k+1].y += r0.z; xv[2*k+1].z += r0.y; xv[2*k+1].w += r0.x;
        }
    }

    // 6) 256-bit streaming stores (2x STG.256 per thread)
    #pragma unroll
    for (int k = 0; k < PAIRS; k++) {
        const int i = (base8 + k * TPB) << 1;
        stg_v8_cs(&out[i], xv[2*k], xv[2*k+1]);
    }
}

// ---------------------------------------------------------------------------
// d_in[0] = x (f32, 16*4096*512), d_in[1] = mask (i32, 16*4096),
// d_in[2] = pe (f32, 5000*256)
// ---------------------------------------------------------------------------
extern "C" void kernel_launch(void* const* d_in, const int* in_sizes, int n_in,
                              void* d_out, int out_size) {
    const float* x    = (const float*)d_in[0];
    const int*   mask = (const int*)d_in[1];
    const float* pe   = (const float*)d_in[2];
    float* out = (float*)d_out;

    const int total_pairs = B_SZ * S_SZ * (D_SZ / 8);       // 4,194,304
    const int blocks = total_pairs / (TPB * PAIRS);         // 8192
    fused_pe_kernel<<<blocks, TPB>>>(
        (const float4*)x, (const int4*)mask, (const float4*)pe, (float4*)out);
}